// round 14
// baseline (speedup 1.0000x reference)
#include <cuda_runtime.h>
#include <cuda_bf16.h>
#include <cstdint>
#include <math.h>

#define D_MODEL 1024
#define NHEADS  16
#define DK      64
#define SEQ     2048
#define BATCH   2
#define MTOT    (BATCH*SEQ)
#define NBH     (BATCH*NHEADS)

// ---- device scratch (no cudaMalloc allowed) ----
__device__ __nv_bfloat16 g_xh[(size_t)MTOT*D_MODEL];
__device__ __nv_bfloat16 g_xl[(size_t)MTOT*D_MODEL];
__device__ __nv_bfloat16 g_Wh[4][(size_t)D_MODEL*D_MODEL];   // q,k,v,o
__device__ __nv_bfloat16 g_Wl[4][(size_t)D_MODEL*D_MODEL];
__device__ __nv_bfloat16 g_Qh[(size_t)NBH*SEQ*DK];
__device__ __nv_bfloat16 g_Ql[(size_t)NBH*SEQ*DK];
__device__ __nv_bfloat16 g_Kh[(size_t)NBH*SEQ*DK];
__device__ __nv_bfloat16 g_Kl[(size_t)NBH*SEQ*DK];
__device__ __nv_bfloat16 g_Vth[(size_t)NBH*DK*SEQ];   // transposed: [bh][d][s]
__device__ __nv_bfloat16 g_Vtl[(size_t)NBH*DK*SEQ];
__device__ __nv_bfloat16 g_Ah[(size_t)MTOT*D_MODEL];  // attention out, split
__device__ __nv_bfloat16 g_Al[(size_t)MTOT*D_MODEL];
__device__ float g_cos[SEQ*(DK/2)];
__device__ float g_sin[SEQ*(DK/2)];

// =============== helpers ===============
__device__ __forceinline__ uint32_t smem_u32(const void* p) {
    uint32_t a;
    asm("{ .reg .u64 t; cvta.to.shared.u64 t, %1; cvt.u32.u64 %0, t; }" : "=r"(a) : "l"(p));
    return a;
}
__device__ __forceinline__ void ldsm4(uint32_t* r, uint32_t a) {
    asm volatile("ldmatrix.sync.aligned.m8n8.x4.shared.b16 {%0,%1,%2,%3}, [%4];"
        : "=r"(r[0]), "=r"(r[1]), "=r"(r[2]), "=r"(r[3]) : "r"(a));
}
__device__ __forceinline__ void mma16816(float* d, const uint32_t* a, uint32_t b0, uint32_t b1) {
    asm volatile("mma.sync.aligned.m16n8k16.row.col.f32.bf16.bf16.f32 "
        "{%0,%1,%2,%3},{%4,%5,%6,%7},{%8,%9},{%0,%1,%2,%3};"
        : "+f"(d[0]), "+f"(d[1]), "+f"(d[2]), "+f"(d[3])
        : "r"(a[0]), "r"(a[1]), "r"(a[2]), "r"(a[3]), "r"(b0), "r"(b1));
}
__device__ __forceinline__ uint32_t cvt2(float a, float b) {
    __nv_bfloat162 t = __floats2bfloat162_rn(a, b);
    return *(uint32_t*)&t;
}
__device__ __forceinline__ uint32_t cvt2res(float a, float b, uint32_t h) {
    __nv_bfloat162 th = *(__nv_bfloat162*)&h;
    return cvt2(a - __low2float(th), b - __high2float(th));
}
#define CP16(d, s) asm volatile("cp.async.cg.shared.global [%0], [%1], 16;" :: "r"(d), "l"(s))
#define CPC()      asm volatile("cp.async.commit_group;" ::: "memory")
#define CPW(n)     asm volatile("cp.async.wait_group %0;" :: "n"(n) : "memory")

// ---------------- RoPE table ----------------
__global__ void rope_table_kernel() {
    int i = blockIdx.x*blockDim.x + threadIdx.x;
    if (i >= SEQ*(DK/2)) return;
    int s = i / (DK/2);
    int j = i % (DK/2);
    double freq = pow(10000.0, -(double)(2*j)/(double)DK);
    double ang  = (double)s * freq;
    g_cos[i] = (float)cos(ang);
    g_sin[i] = (float)sin(ang);
}

// exp2(x - 12) with the shift folded into the range-reduction magic constant.
__device__ __forceinline__ float exp2m12(float x) {
    x = fmaxf(x, -113.0f);
    float t = x + 12582900.0f;               // (x-12) + 1.5*2^23
    int   e = __float_as_int(t) << 23;
    float f = x - (t - 12582900.0f);
    float p = 1.5402387e-4f;
    p = fmaf(p, f, 1.3333558e-3f);
    p = fmaf(p, f, 9.6181291e-3f);
    p = fmaf(p, f, 5.5504109e-2f);
    p = fmaf(p, f, 2.4022651e-1f);
    p = fmaf(p, f, 6.9314718e-1f);
    p = fmaf(p, f, 1.0f);
    return __int_as_float(__float_as_int(p) + e);
}

// ---------------- fp32 -> bf16 h/l split (single merged pre-pass) ----------------
__global__ void split_all_kernel(const float* __restrict__ x,
                                 const float* __restrict__ Wq,
                                 const float* __restrict__ Wk,
                                 const float* __restrict__ Wv,
                                 const float* __restrict__ Wo)
{
    size_t i = ((size_t)blockIdx.x*blockDim.x + threadIdx.x) * 4;
    const float* s;
    __nv_bfloat16 *h, *l;
    size_t off;
    const size_t NX = (size_t)MTOT*D_MODEL;
    if (i < NX) {
        s = x; h = g_xh; l = g_xl; off = i;
    } else {
        size_t j = i - NX;
        int w = (int)(j >> 20);
        off = j & ((1u << 20) - 1);
        s = (w == 0) ? Wq : (w == 1) ? Wk : (w == 2) ? Wv : Wo;
        h = g_Wh[w]; l = g_Wl[w];
    }
    float4 v = *(const float4*)(s + off);
    uint32_t h0 = cvt2(v.x, v.y), h1 = cvt2(v.z, v.w);
    uint32_t l0 = cvt2res(v.x, v.y, h0), l1 = cvt2res(v.z, v.w, h1);
    *(uint2*)(h + off) = make_uint2(h0, h1);
    *(uint2*)(l + off) = make_uint2(l0, l1);
}

// =============== bf16 pre-split GEMM core (CTA 256x128, warp 64x64, K-chunk 64) ===============
#define GST  110592u
#define G_AL 36864u
#define G_BH 73728u
#define G_BL 92160u

__device__ __forceinline__ void gemm_load_stage(
    uint32_t stg, const __nv_bfloat16* Ah, const __nv_bfloat16* Al,
    const __nv_bfloat16* Bh, const __nv_bfloat16* Bl, int koff, int tid)
{
    #pragma unroll
    for (int i = 0; i < 8; i++) {                    // A: 256 rows x 8 chunks
        int idx = tid + i*256;
        int r = idx >> 3, cb = idx & 7;
        uint32_t dst = stg + (uint32_t)r*144u + (uint32_t)cb*16u;
        size_t src = (size_t)r*D_MODEL + koff + cb*8;
        CP16(dst,        Ah + src);
        CP16(dst + G_AL, Al + src);
    }
    #pragma unroll
    for (int i = 0; i < 4; i++) {                    // B: 128 rows x 8 chunks
        int idx = tid + i*256;
        int r = idx >> 3, cb = idx & 7;
        uint32_t dst = stg + G_BH + (uint32_t)r*144u + (uint32_t)cb*16u;
        size_t src = (size_t)r*D_MODEL + koff + cb*8;
        CP16(dst,                  Bh + src);
        CP16(dst + (G_BL - G_BH),  Bl + src);
    }
}

__device__ __forceinline__ void bf16_gemm_core2(
    const __nv_bfloat16* __restrict__ Ah, const __nv_bfloat16* __restrict__ Al,
    const __nv_bfloat16* __restrict__ Bh, const __nv_bfloat16* __restrict__ Bl,
    char* sm, int tid, float acc[4][8][4])
{
    const int lane = tid & 31, warp = tid >> 5;
    const int wm = warp >> 1, wn = warp & 1;
    const uint32_t sb = smem_u32(sm);
    const uint32_t a_off = (uint32_t)(wm*64 + (lane & 15))*144u + (uint32_t)((lane >> 4)*16);
    const uint32_t b_off = (uint32_t)(wn*64 + (lane & 7) + ((lane >> 4)*8))*144u
                         + (uint32_t)(((lane >> 3) & 1)*16);

    #pragma unroll
    for (int mt = 0; mt < 4; mt++)
        #pragma unroll
        for (int nt = 0; nt < 8; nt++)
            #pragma unroll
            for (int q = 0; q < 4; q++) acc[mt][nt][q] = 0.f;

    gemm_load_stage(sb, Ah, Al, Bh, Bl, 0, tid);
    CPC();

    for (int c = 0; c < 16; c++) {
        if (c < 15) {
            gemm_load_stage(sb + ((c+1) & 1)*GST, Ah, Al, Bh, Bl, (c+1)*64, tid);
            CPC();
            CPW(1);
        } else {
            CPW(0);
        }
        __syncthreads();

        const uint32_t stg = sb + (c & 1)*GST;
        #pragma unroll
        for (int kc = 0; kc < 4; kc++) {
            uint32_t aH[4][4], aL[4][4];
            #pragma unroll
            for (int j = 0; j < 4; j++) {
                ldsm4(aH[j], stg + a_off + j*2304u + kc*32);
                ldsm4(aL[j], stg + G_AL + a_off + j*2304u + kc*32);
            }
            #pragma unroll
            for (int g = 0; g < 4; g++) {
                uint32_t bh4[4], bl4[4];
                ldsm4(bh4, stg + G_BH + b_off + g*2304u + kc*32);
                ldsm4(bl4, stg + G_BL + b_off + g*2304u + kc*32);
                #pragma unroll
                for (int sub = 0; sub < 2; sub++) {
                    int nt = g*2 + sub;
                    uint32_t b0 = bh4[sub*2], b1 = bh4[sub*2+1];
                    uint32_t c0 = bl4[sub*2], c1 = bl4[sub*2+1];
                    #pragma unroll
                    for (int mt = 0; mt < 4; mt++) {
                        mma16816(acc[mt][nt], aH[mt], b0, b1);
                        mma16816(acc[mt][nt], aL[mt], b0, b1);
                        mma16816(acc[mt][nt], aH[mt], c0, c1);
                    }
                }
            }
        }
        __syncthreads();
    }
}

// =============== fused QKV GEMM + RoPE + bf16-split store ===============
__global__ __launch_bounds__(256) void tc_qkv_kernel()
{
    extern __shared__ char sm[];
    const int tid = threadIdx.x;
    const int z = blockIdx.z;
    const int m0 = blockIdx.y * 256;
    const int n0 = blockIdx.x * 128;
    const float SCQ = 0.18033688011112042f;   // log2(e)/sqrt(64)

    float acc[4][8][4];
    bf16_gemm_core2(g_xh + (size_t)m0*D_MODEL, g_xl + (size_t)m0*D_MODEL,
                    g_Wh[z] + (size_t)n0*D_MODEL, g_Wl[z] + (size_t)n0*D_MODEL,
                    sm, tid, acc);

    const int lane = tid & 31, warp = tid >> 5;
    const int wm = warp >> 1, wn = warp & 1;

    #pragma unroll
    for (int mt = 0; mt < 4; mt++) {
        #pragma unroll
        for (int rr = 0; rr < 2; rr++) {
            int m = m0 + wm*64 + mt*16 + (lane >> 2) + rr*8;
            int b = m >> 11, s = m & (SEQ-1);
            int bh = b*NHEADS;
            #pragma unroll
            for (int nt = 0; nt < 8; nt++) {
                int n = n0 + wn*64 + nt*8 + (lane & 3)*2;
                int h = n >> 6, d = n & 63;
                float x1 = acc[mt][nt][rr*2], x2 = acc[mt][nt][rr*2+1];
                if (z < 2) {
                    float cv = g_cos[s*(DK/2) + (d >> 1)];
                    float sv = g_sin[s*(DK/2) + (d >> 1)];
                    float o1 = cv*x1 - sv*x2;
                    float o2 = sv*x1 + cv*x2;
                    if (z == 0) { o1 *= SCQ; o2 *= SCQ; }
                    uint32_t hv = cvt2(o1, o2);
                    uint32_t lv = cvt2res(o1, o2, hv);
                    size_t base = ((size_t)(bh + h)*SEQ + s)*DK + d;
                    if (z == 0) {
                        *(uint32_t*)(g_Qh + base) = hv;
                        *(uint32_t*)(g_Ql + base) = lv;
                    } else {
                        *(uint32_t*)(g_Kh + base) = hv;
                        *(uint32_t*)(g_Kl + base) = lv;
                    }
                } else {
                    size_t tb = ((size_t)(bh + h)*DK + d)*SEQ + s;
                    __nv_bfloat16 h1 = __float2bfloat16_rn(x1);
                    __nv_bfloat16 h2 = __float2bfloat16_rn(x2);
                    g_Vth[tb]       = h1;
                    g_Vth[tb + SEQ] = h2;
                    g_Vtl[tb]       = __float2bfloat16_rn(x1 - __bfloat162float(h1));
                    g_Vtl[tb + SEQ] = __float2bfloat16_rn(x2 - __bfloat162float(h2));
                }
            }
        }
    }
}

// =============== output projection ===============
__global__ __launch_bounds__(256) void tc_out_kernel(float* __restrict__ out)
{
    extern __shared__ char sm[];
    const int tid = threadIdx.x;
    const int m0 = blockIdx.y * 256;
    const int n0 = blockIdx.x * 128;

    float acc[4][8][4];
    bf16_gemm_core2(g_Ah + (size_t)m0*D_MODEL, g_Al + (size_t)m0*D_MODEL,
                    g_Wh[3] + (size_t)n0*D_MODEL, g_Wl[3] + (size_t)n0*D_MODEL,
                    sm, tid, acc);

    const int lane = tid & 31, warp = tid >> 5;
    const int wm = warp >> 1, wn = warp & 1;

    #pragma unroll
    for (int mt = 0; mt < 4; mt++) {
        #pragma unroll
        for (int rr = 0; rr < 2; rr++) {
            int m = m0 + wm*64 + mt*16 + (lane >> 2) + rr*8;
            #pragma unroll
            for (int nt = 0; nt < 8; nt++) {
                int n = n0 + wn*64 + nt*8 + (lane & 3)*2;
                *(float2*)(out + (size_t)m*D_MODEL + n) =
                    make_float2(acc[mt][nt][rr*2], acc[mt][nt][rr*2+1]);
            }
        }
    }
}

// =============== flash attention (BN=128, 512 threads, kv-split warp groups) ===============
// 16 warps: mw = w&7 (16 q-rows each), kg = w>>3 (kv half: 64 kv each).
// 2 stages (71680B each) + persistent Q (36864B) = 180224B.
#define FSTG  71680u
#define F_KL  18432u
#define F_VH  36864u
#define F_VL  54272u

__device__ __forceinline__ void flash_load_kv512(
    uint32_t st, const __nv_bfloat16* Khg, const __nv_bfloat16* Klg,
    const __nv_bfloat16* Vhg, const __nv_bfloat16* Vlg, int kt, int tid)
{
    const __nv_bfloat16* kh = Khg + (size_t)kt*128*DK;
    const __nv_bfloat16* kl = Klg + (size_t)kt*128*DK;
    #pragma unroll
    for (int i = 0; i < 2; i++) {
        int idx = tid + i*512;
        int r = idx >> 3, c = idx & 7;                 // 128 rows x 8 chunks
        CP16(st + r*144 + c*16,         kh + r*64 + c*8);
        CP16(st + F_KL + r*144 + c*16,  kl + r*64 + c*8);
    }
    #pragma unroll
    for (int i = 0; i < 2; i++) {
        int idx = tid + i*512;
        int r = idx >> 4, c = idx & 15;                // 64 rows x 16 chunks
        CP16(st + F_VH + r*272 + c*16, Vhg + (size_t)r*SEQ + kt*128 + c*8);
        CP16(st + F_VL + r*272 + c*16, Vlg + (size_t)r*SEQ + kt*128 + c*8);
    }
}

__global__ __launch_bounds__(512,1) void flash_kernel()
{
    extern __shared__ char sm[];
    const uint32_t sb = smem_u32(sm);
    const int tid = threadIdx.x;
    const int lane = tid & 31, w = tid >> 5;
    const int mw = w & 7, kg = w >> 3;
    const int qt = gridDim.x - 1 - (int)blockIdx.x;    // long blocks first
    const int bh = blockIdx.y;
    const int b = bh >> 4, h = bh & 15;

    const __nv_bfloat16* Qhg = g_Qh + (size_t)bh*SEQ*DK + (size_t)qt*128*DK;
    const __nv_bfloat16* Qlg = g_Ql + (size_t)bh*SEQ*DK + (size_t)qt*128*DK;
    const __nv_bfloat16* Khg = g_Kh + (size_t)bh*SEQ*DK;
    const __nv_bfloat16* Klg = g_Kl + (size_t)bh*SEQ*DK;
    const __nv_bfloat16* Vhg = g_Vth + (size_t)bh*DK*SEQ;
    const __nv_bfloat16* Vlg = g_Vtl + (size_t)bh*DK*SEQ;

    const uint32_t QH = sb + 2*FSTG, QL = QH + 18432u;

    // Q load (persistent), then KV stage 0
    #pragma unroll
    for (int i = 0; i < 2; i++) {
        int idx = tid + i*512;
        int r = idx >> 3, c = idx & 7;
        CP16(QH + r*144 + c*16, Qhg + r*64 + c*8);
        CP16(QL + r*144 + c*16, Qlg + r*64 + c*8);
    }
    CPC();
    flash_load_kv512(sb, Khg, Klg, Vhg, Vlg, 0, tid);
    CPC();

    // fragment bases
    const uint32_t a_off  = (uint32_t)((mw*16 + (lane & 15))*144) + (uint32_t)((lane >> 4)*16);
    const uint32_t kb_off = (uint32_t)((kg*64 + (lane & 7) + ((lane >> 4)*8))*144)
                          + (uint32_t)(((lane >> 3) & 1)*16);
    const uint32_t vb_off = (uint32_t)(((lane & 7) + ((lane >> 4)*8))*272)
                          + (uint32_t)(((lane >> 3) & 1)*16) + (uint32_t)kg*128u;

    float o[8][4];
    #pragma unroll
    for (int dt = 0; dt < 8; dt++)
        #pragma unroll
        for (int q = 0; q < 4; q++) o[dt][q] = 0.f;
    float l0 = 0.f, l1 = 0.f;

    for (int kt = 0; kt <= qt; kt++) {
        if (kt < qt) {
            flash_load_kv512(sb + ((kt+1) & 1)*FSTG, Khg, Klg, Vhg, Vlg, kt + 1, tid);
            CPC();
            CPW(1);
        } else {
            CPW(0);
        }
        __syncthreads();

        const uint32_t st = sb + (kt & 1)*FSTG;

        // ---- QK^T: this warp's kv-half (8 n-tiles), Q frags reloaded from smem ----
        float acc[8][4];
        #pragma unroll
        for (int nt = 0; nt < 8; nt++)
            #pragma unroll
            for (int q = 0; q < 4; q++) acc[nt][q] = 0.f;

        #pragma unroll
        for (int kc = 0; kc < 4; kc++) {
            uint32_t qh4[4], ql4[4];
            ldsm4(qh4, QH + a_off + kc*32);
            ldsm4(ql4, QL + a_off + kc*32);
            #pragma unroll
            for (int g = 0; g < 4; g++) {
                uint32_t bh4[4], bl4[4];
                ldsm4(bh4, st + kb_off + g*2304u + kc*32);
                ldsm4(bl4, st + F_KL + kb_off + g*2304u + kc*32);
                #pragma unroll
                for (int sub = 0; sub < 2; sub++) {
                    int nt = g*2 + sub;
                    mma16816(acc[nt], qh4, bh4[sub*2], bh4[sub*2+1]);
                    mma16816(acc[nt], ql4, bh4[sub*2], bh4[sub*2+1]);
                    mma16816(acc[nt], qh4, bl4[sub*2], bl4[sub*2+1]);
                }
            }
        }

        // ---- causal mask (diagonal tile only) ----
        if (kt == qt) {
            #pragma unroll
            for (int nt = 0; nt < 8; nt++)
                #pragma unroll
                for (int j = 0; j < 4; j++) {
                    int kj = kt*128 + kg*64 + nt*8 + ((lane & 3) << 1) + (j & 1);
                    int qi = qt*128 + mw*16 + (lane >> 2) + ((j >> 1) << 3);
                    if (kj > qi) acc[nt][j] = -1e30f;
                }
        }

        // ---- static-max softmax ----
        #pragma unroll
        for (int nt = 0; nt < 8; nt++) {
            acc[nt][0] = exp2m12(acc[nt][0]);
            acc[nt][1] = exp2m12(acc[nt][1]);
            acc[nt][2] = exp2m12(acc[nt][2]);
            acc[nt][3] = exp2m12(acc[nt][3]);
            l0 += acc[nt][0] + acc[nt][1];
            l1 += acc[nt][2] + acc[nt][3];
        }

        // ---- PV over this warp's kv-half: 4 k-chunks of 16 kv ----
        #pragma unroll
        for (int kc = 0; kc < 4; kc++) {
            uint32_t pah[4], pal[4];
            pah[0] = cvt2(acc[2*kc][0],   acc[2*kc][1]);   pal[0] = cvt2res(acc[2*kc][0],   acc[2*kc][1],   pah[0]);
            pah[1] = cvt2(acc[2*kc][2],   acc[2*kc][3]);   pal[1] = cvt2res(acc[2*kc][2],   acc[2*kc][3],   pah[1]);
            pah[2] = cvt2(acc[2*kc+1][0], acc[2*kc+1][1]); pal[2] = cvt2res(acc[2*kc+1][0], acc[2*kc+1][1], pah[2]);
            pah[3] = cvt2(acc[2*kc+1][2], acc[2*kc+1][3]); pal[3] = cvt2res(acc[2*kc+1][2], acc[2*kc+1][3], pah[3]);
            uint32_t vbh[4][4], vbl[4][4];
            #pragma unroll
            for (int g = 0; g < 4; g++) {
                ldsm4(vbh[g], st + F_VH + vb_off + g*4352u + kc*32);
                ldsm4(vbl[g], st + F_VL + vb_off + g*4352u + kc*32);
            }
            #pragma unroll
            for (int dt = 0; dt < 8; dt++) {
                uint32_t b0 = vbh[dt>>1][(dt&1)*2], b1 = vbh[dt>>1][(dt&1)*2+1];
                uint32_t c0 = vbl[dt>>1][(dt&1)*2], c1 = vbl[dt>>1][(dt&1)*2+1];
                mma16816(o[dt], pah, b0, b1);
                mma16816(o[dt], pal, b0, b1);
                mma16816(o[dt], pah, c0, c1);
            }
        }
        __syncthreads();
    }

    // ---- cross-group reduction: kg=1 warps publish o,l; kg=0 warps combine ----
    float* red = (float*)sm;    // stage region reuse; 8 warps x 32 lanes x 36 floats = 36KB
    if (kg == 1) {
        float* dst = red + ((size_t)(mw*32 + lane))*36;
        #pragma unroll
        for (int dt = 0; dt < 8; dt++)
            #pragma unroll
            for (int q = 0; q < 4; q++) dst[dt*4+q] = o[dt][q];
        dst[32] = l0;
        dst[33] = l1;
    }
    __syncthreads();
    if (kg == 0) {
        const float* src = red + ((size_t)(mw*32 + lane))*36;
        #pragma unroll
        for (int dt = 0; dt < 8; dt++)
            #pragma unroll
            for (int q = 0; q < 4; q++) o[dt][q] += src[dt*4+q];
        l0 += src[32];
        l1 += src[33];

        l0 += __shfl_xor_sync(0xffffffffu, l0, 1);
        l0 += __shfl_xor_sync(0xffffffffu, l0, 2);
        l1 += __shfl_xor_sync(0xffffffffu, l1, 1);
        l1 += __shfl_xor_sync(0xffffffffu, l1, 2);
        float inv0 = 1.0f / l0, inv1 = 1.0f / l1;
        int r0 = qt*128 + mw*16 + (lane >> 2);
        #pragma unroll
        for (int dt = 0; dt < 8; dt++) {
            int d = dt*8 + (lane & 3)*2;
            size_t p0 = ((size_t)b*SEQ + r0)*D_MODEL + h*64 + d;
            size_t p1 = p0 + (size_t)8*D_MODEL;
            float a0 = o[dt][0]*inv0, a1 = o[dt][1]*inv0;
            float a2 = o[dt][2]*inv1, a3 = o[dt][3]*inv1;
            uint32_t h0 = cvt2(a0, a1), h1v = cvt2(a2, a3);
            *(uint32_t*)(g_Ah + p0) = h0;
            *(uint32_t*)(g_Al + p0) = cvt2res(a0, a1, h0);
            *(uint32_t*)(g_Ah + p1) = h1v;
            *(uint32_t*)(g_Al + p1) = cvt2res(a2, a3, h1v);
        }
    }
}

// ---------------- launch ----------------
extern "C" void kernel_launch(void* const* d_in, const int* in_sizes, int n_in,
                              void* d_out, int out_size)
{
    const float* x  = (const float*)d_in[0];
    const float* Wq = (const float*)d_in[1];
    const float* Wk = (const float*)d_in[2];
    const float* Wv = (const float*)d_in[3];
    const float* Wo = (const float*)d_in[4];
    float* out = (float*)d_out;

    const int gemm_smem  = 2*GST;                 // 221184 B
    const int flash_smem = 2*FSTG + 2*18432;      // 180224 B
    cudaFuncSetAttribute(tc_qkv_kernel, cudaFuncAttributeMaxDynamicSharedMemorySize, gemm_smem);
    cudaFuncSetAttribute(tc_out_kernel, cudaFuncAttributeMaxDynamicSharedMemorySize, gemm_smem);
    cudaFuncSetAttribute(flash_kernel,  cudaFuncAttributeMaxDynamicSharedMemorySize, flash_smem);

    rope_table_kernel<<<(SEQ*(DK/2) + 255)/256, 256>>>();

    const size_t NTOT = (size_t)MTOT*D_MODEL + 4*(size_t)D_MODEL*D_MODEL;   // 8M
    split_all_kernel<<<(int)(NTOT/4/256), 256>>>(x, Wq, Wk, Wv, Wo);

    dim3 g1(D_MODEL/128, MTOT/256, 3);
    tc_qkv_kernel<<<g1, 256, gemm_smem>>>();

    dim3 g2(SEQ/128, NBH);
    flash_kernel<<<g2, 512, flash_smem>>>();

    dim3 g3(D_MODEL/128, MTOT/256);
    tc_out_kernel<<<g3, 256, gemm_smem>>>(out);
}

// round 15
// speedup vs baseline: 1.0305x; 1.0305x over previous
#include <cuda_runtime.h>
#include <cuda_bf16.h>
#include <cstdint>
#include <math.h>

#define D_MODEL 1024
#define NHEADS  16
#define DK      64
#define SEQ     2048
#define BATCH   2
#define MTOT    (BATCH*SEQ)
#define NBH     (BATCH*NHEADS)

// ---- device scratch (no cudaMalloc allowed) ----
__device__ __nv_bfloat16 g_xh[(size_t)MTOT*D_MODEL];
__device__ __nv_bfloat16 g_xl[(size_t)MTOT*D_MODEL];
__device__ __nv_bfloat16 g_Wh[4][(size_t)D_MODEL*D_MODEL];   // q,k,v,o
__device__ __nv_bfloat16 g_Wl[4][(size_t)D_MODEL*D_MODEL];
__device__ __nv_bfloat16 g_Qh[(size_t)NBH*SEQ*DK];
__device__ __nv_bfloat16 g_Ql[(size_t)NBH*SEQ*DK];
__device__ __nv_bfloat16 g_Kh[(size_t)NBH*SEQ*DK];
__device__ __nv_bfloat16 g_Kl[(size_t)NBH*SEQ*DK];
__device__ __nv_bfloat16 g_Vth[(size_t)NBH*DK*SEQ];   // transposed: [bh][d][s]
__device__ __nv_bfloat16 g_Vtl[(size_t)NBH*DK*SEQ];
__device__ __nv_bfloat16 g_Ah[(size_t)MTOT*D_MODEL];  // attention out, split
__device__ __nv_bfloat16 g_Al[(size_t)MTOT*D_MODEL];
__device__ float g_cos[SEQ*(DK/2)];
__device__ float g_sin[SEQ*(DK/2)];

// =============== helpers ===============
__device__ __forceinline__ uint32_t smem_u32(const void* p) {
    uint32_t a;
    asm("{ .reg .u64 t; cvta.to.shared.u64 t, %1; cvt.u32.u64 %0, t; }" : "=r"(a) : "l"(p));
    return a;
}
__device__ __forceinline__ void ldsm4(uint32_t* r, uint32_t a) {
    asm volatile("ldmatrix.sync.aligned.m8n8.x4.shared.b16 {%0,%1,%2,%3}, [%4];"
        : "=r"(r[0]), "=r"(r[1]), "=r"(r[2]), "=r"(r[3]) : "r"(a));
}
__device__ __forceinline__ void mma16816(float* d, const uint32_t* a, uint32_t b0, uint32_t b1) {
    asm volatile("mma.sync.aligned.m16n8k16.row.col.f32.bf16.bf16.f32 "
        "{%0,%1,%2,%3},{%4,%5,%6,%7},{%8,%9},{%0,%1,%2,%3};"
        : "+f"(d[0]), "+f"(d[1]), "+f"(d[2]), "+f"(d[3])
        : "r"(a[0]), "r"(a[1]), "r"(a[2]), "r"(a[3]), "r"(b0), "r"(b1));
}
__device__ __forceinline__ uint32_t cvt2(float a, float b) {
    __nv_bfloat162 t = __floats2bfloat162_rn(a, b);
    return *(uint32_t*)&t;
}
__device__ __forceinline__ uint32_t cvt2res(float a, float b, uint32_t h) {
    __nv_bfloat162 th = *(__nv_bfloat162*)&h;
    return cvt2(a - __low2float(th), b - __high2float(th));
}
#define CP16(d, s) asm volatile("cp.async.cg.shared.global [%0], [%1], 16;" :: "r"(d), "l"(s))
#define CPC()      asm volatile("cp.async.commit_group;" ::: "memory")
#define CPW(n)     asm volatile("cp.async.wait_group %0;" :: "n"(n) : "memory")

// ---------------- RoPE table ----------------
__global__ void rope_table_kernel() {
    int i = blockIdx.x*blockDim.x + threadIdx.x;
    if (i >= SEQ*(DK/2)) return;
    int s = i / (DK/2);
    int j = i % (DK/2);
    double freq = pow(10000.0, -(double)(2*j)/(double)DK);
    double ang  = (double)s * freq;
    g_cos[i] = (float)cos(ang);
    g_sin[i] = (float)sin(ang);
}

// exp2(x - 12) with the shift folded into the range-reduction magic constant.
__device__ __forceinline__ float exp2m12(float x) {
    x = fmaxf(x, -113.0f);
    float t = x + 12582900.0f;               // (x-12) + 1.5*2^23
    int   e = __float_as_int(t) << 23;
    float f = x - (t - 12582900.0f);
    float p = 1.5402387e-4f;
    p = fmaf(p, f, 1.3333558e-3f);
    p = fmaf(p, f, 9.6181291e-3f);
    p = fmaf(p, f, 5.5504109e-2f);
    p = fmaf(p, f, 2.4022651e-1f);
    p = fmaf(p, f, 6.9314718e-1f);
    p = fmaf(p, f, 1.0f);
    return __int_as_float(__float_as_int(p) + e);
}

// ---------------- fp32 -> bf16 h/l split (single merged pre-pass) ----------------
__global__ void split_all_kernel(const float* __restrict__ x,
                                 const float* __restrict__ Wq,
                                 const float* __restrict__ Wk,
                                 const float* __restrict__ Wv,
                                 const float* __restrict__ Wo)
{
    size_t i = ((size_t)blockIdx.x*blockDim.x + threadIdx.x) * 4;
    const float* s;
    __nv_bfloat16 *h, *l;
    size_t off;
    const size_t NX = (size_t)MTOT*D_MODEL;
    if (i < NX) {
        s = x; h = g_xh; l = g_xl; off = i;
    } else {
        size_t j = i - NX;
        int w = (int)(j >> 20);
        off = j & ((1u << 20) - 1);
        s = (w == 0) ? Wq : (w == 1) ? Wk : (w == 2) ? Wv : Wo;
        h = g_Wh[w]; l = g_Wl[w];
    }
    float4 v = *(const float4*)(s + off);
    uint32_t h0 = cvt2(v.x, v.y), h1 = cvt2(v.z, v.w);
    uint32_t l0 = cvt2res(v.x, v.y, h0), l1 = cvt2res(v.z, v.w, h1);
    *(uint2*)(h + off) = make_uint2(h0, h1);
    *(uint2*)(l + off) = make_uint2(l0, l1);
}

// =============== bf16 pre-split GEMM core (CTA 256x128, 512 thr, warp 64x32) ===============
#define GST  110592u
#define G_AL 36864u
#define G_BH 73728u
#define G_BL 92160u

__device__ __forceinline__ void gemm_load_stage(
    uint32_t stg, const __nv_bfloat16* Ah, const __nv_bfloat16* Al,
    const __nv_bfloat16* Bh, const __nv_bfloat16* Bl, int koff, int tid)
{
    #pragma unroll
    for (int i = 0; i < 4; i++) {                    // A: 256 rows x 8 chunks
        int idx = tid + i*512;
        int r = idx >> 3, cb = idx & 7;
        uint32_t dst = stg + (uint32_t)r*144u + (uint32_t)cb*16u;
        size_t src = (size_t)r*D_MODEL + koff + cb*8;
        CP16(dst,        Ah + src);
        CP16(dst + G_AL, Al + src);
    }
    #pragma unroll
    for (int i = 0; i < 2; i++) {                    // B: 128 rows x 8 chunks
        int idx = tid + i*512;
        int r = idx >> 3, cb = idx & 7;
        uint32_t dst = stg + G_BH + (uint32_t)r*144u + (uint32_t)cb*16u;
        size_t src = (size_t)r*D_MODEL + koff + cb*8;
        CP16(dst,                  Bh + src);
        CP16(dst + (G_BL - G_BH),  Bl + src);
    }
}

__device__ __forceinline__ void bf16_gemm_core2(
    const __nv_bfloat16* __restrict__ Ah, const __nv_bfloat16* __restrict__ Al,
    const __nv_bfloat16* __restrict__ Bh, const __nv_bfloat16* __restrict__ Bl,
    char* sm, int tid, float acc[4][4][4])
{
    const int lane = tid & 31, warp = tid >> 5;
    const int wm = warp >> 2, wn = warp & 3;          // 4m x 4n
    const uint32_t sb = smem_u32(sm);
    const uint32_t a_off = (uint32_t)(wm*64 + (lane & 15))*144u + (uint32_t)((lane >> 4)*16);
    const uint32_t b_off = (uint32_t)(wn*32 + (lane & 7) + ((lane >> 4)*8))*144u
                         + (uint32_t)(((lane >> 3) & 1)*16);

    #pragma unroll
    for (int mt = 0; mt < 4; mt++)
        #pragma unroll
        for (int nt = 0; nt < 4; nt++)
            #pragma unroll
            for (int q = 0; q < 4; q++) acc[mt][nt][q] = 0.f;

    gemm_load_stage(sb, Ah, Al, Bh, Bl, 0, tid);
    CPC();

    for (int c = 0; c < 16; c++) {
        if (c < 15) {
            gemm_load_stage(sb + ((c+1) & 1)*GST, Ah, Al, Bh, Bl, (c+1)*64, tid);
            CPC();
            CPW(1);
        } else {
            CPW(0);
        }
        __syncthreads();

        const uint32_t stg = sb + (c & 1)*GST;
        #pragma unroll
        for (int kc = 0; kc < 4; kc++) {
            uint32_t aH[4][4], aL[4][4];
            #pragma unroll
            for (int j = 0; j < 4; j++) {
                ldsm4(aH[j], stg + a_off + j*2304u + kc*32);
                ldsm4(aL[j], stg + G_AL + a_off + j*2304u + kc*32);
            }
            #pragma unroll
            for (int g = 0; g < 2; g++) {
                uint32_t bh4[4], bl4[4];
                ldsm4(bh4, stg + G_BH + b_off + g*2304u + kc*32);
                ldsm4(bl4, stg + G_BL + b_off + g*2304u + kc*32);
                #pragma unroll
                for (int sub = 0; sub < 2; sub++) {
                    int nt = g*2 + sub;
                    uint32_t b0 = bh4[sub*2], b1 = bh4[sub*2+1];
                    uint32_t c0 = bl4[sub*2], c1 = bl4[sub*2+1];
                    #pragma unroll
                    for (int mt = 0; mt < 4; mt++) {
                        mma16816(acc[mt][nt], aH[mt], b0, b1);
                        mma16816(acc[mt][nt], aL[mt], b0, b1);
                        mma16816(acc[mt][nt], aH[mt], c0, c1);
                    }
                }
            }
        }
        __syncthreads();
    }
}

// =============== fused QKV GEMM + RoPE + bf16-split store ===============
__global__ __launch_bounds__(512) void tc_qkv_kernel()
{
    extern __shared__ char sm[];
    const int tid = threadIdx.x;
    const int z = blockIdx.z;
    const int m0 = blockIdx.y * 256;
    const int n0 = blockIdx.x * 128;
    const float SCQ = 0.18033688011112042f;   // log2(e)/sqrt(64)

    float acc[4][4][4];
    bf16_gemm_core2(g_xh + (size_t)m0*D_MODEL, g_xl + (size_t)m0*D_MODEL,
                    g_Wh[z] + (size_t)n0*D_MODEL, g_Wl[z] + (size_t)n0*D_MODEL,
                    sm, tid, acc);

    const int lane = tid & 31, warp = tid >> 5;
    const int wm = warp >> 2, wn = warp & 3;

    #pragma unroll
    for (int mt = 0; mt < 4; mt++) {
        #pragma unroll
        for (int rr = 0; rr < 2; rr++) {
            int m = m0 + wm*64 + mt*16 + (lane >> 2) + rr*8;
            int b = m >> 11, s = m & (SEQ-1);
            int bh = b*NHEADS;
            #pragma unroll
            for (int nt = 0; nt < 4; nt++) {
                int n = n0 + wn*32 + nt*8 + (lane & 3)*2;
                int h = n >> 6, d = n & 63;
                float x1 = acc[mt][nt][rr*2], x2 = acc[mt][nt][rr*2+1];
                if (z < 2) {
                    float cv = g_cos[s*(DK/2) + (d >> 1)];
                    float sv = g_sin[s*(DK/2) + (d >> 1)];
                    float o1 = cv*x1 - sv*x2;
                    float o2 = sv*x1 + cv*x2;
                    if (z == 0) { o1 *= SCQ; o2 *= SCQ; }
                    uint32_t hv = cvt2(o1, o2);
                    uint32_t lv = cvt2res(o1, o2, hv);
                    size_t base = ((size_t)(bh + h)*SEQ + s)*DK + d;
                    if (z == 0) {
                        *(uint32_t*)(g_Qh + base) = hv;
                        *(uint32_t*)(g_Ql + base) = lv;
                    } else {
                        *(uint32_t*)(g_Kh + base) = hv;
                        *(uint32_t*)(g_Kl + base) = lv;
                    }
                } else {
                    size_t tb = ((size_t)(bh + h)*DK + d)*SEQ + s;
                    __nv_bfloat16 h1 = __float2bfloat16_rn(x1);
                    __nv_bfloat16 h2 = __float2bfloat16_rn(x2);
                    g_Vth[tb]       = h1;
                    g_Vth[tb + SEQ] = h2;
                    g_Vtl[tb]       = __float2bfloat16_rn(x1 - __bfloat162float(h1));
                    g_Vtl[tb + SEQ] = __float2bfloat16_rn(x2 - __bfloat162float(h2));
                }
            }
        }
    }
}

// =============== output projection ===============
__global__ __launch_bounds__(512) void tc_out_kernel(float* __restrict__ out)
{
    extern __shared__ char sm[];
    const int tid = threadIdx.x;
    const int m0 = blockIdx.y * 256;
    const int n0 = blockIdx.x * 128;

    float acc[4][4][4];
    bf16_gemm_core2(g_Ah + (size_t)m0*D_MODEL, g_Al + (size_t)m0*D_MODEL,
                    g_Wh[3] + (size_t)n0*D_MODEL, g_Wl[3] + (size_t)n0*D_MODEL,
                    sm, tid, acc);

    const int lane = tid & 31, warp = tid >> 5;
    const int wm = warp >> 2, wn = warp & 3;

    #pragma unroll
    for (int mt = 0; mt < 4; mt++) {
        #pragma unroll
        for (int rr = 0; rr < 2; rr++) {
            int m = m0 + wm*64 + mt*16 + (lane >> 2) + rr*8;
            #pragma unroll
            for (int nt = 0; nt < 4; nt++) {
                int n = n0 + wn*32 + nt*8 + (lane & 3)*2;
                *(float2*)(out + (size_t)m*D_MODEL + n) =
                    make_float2(acc[mt][nt][rr*2], acc[mt][nt][rr*2+1]);
            }
        }
    }
}

// =============== flash attention (R13-proven: BN=128, 256 thr, 3-stage) ===============
#define FSTG  71680u
#define F_KL  18432u
#define F_VH  36864u
#define F_VL  54272u

__device__ __forceinline__ void flash_load_kv(
    uint32_t st, const __nv_bfloat16* Khg, const __nv_bfloat16* Klg,
    const __nv_bfloat16* Vhg, const __nv_bfloat16* Vlg, int kt, int tid)
{
    const __nv_bfloat16* kh = Khg + (size_t)kt*128*DK;
    const __nv_bfloat16* kl = Klg + (size_t)kt*128*DK;
    #pragma unroll
    for (int i = 0; i < 4; i++) {
        int idx = tid + i*256;
        int r = idx >> 3, c = idx & 7;
        CP16(st + r*144 + c*16,         kh + r*64 + c*8);
        CP16(st + F_KL + r*144 + c*16,  kl + r*64 + c*8);
    }
    #pragma unroll
    for (int i = 0; i < 4; i++) {
        int idx = tid + i*256;
        int r = idx >> 4, c = idx & 15;
        CP16(st + F_VH + r*272 + c*16, Vhg + (size_t)r*SEQ + kt*128 + c*8);
        CP16(st + F_VL + r*272 + c*16, Vlg + (size_t)r*SEQ + kt*128 + c*8);
    }
}

__global__ __launch_bounds__(256) void flash_kernel()
{
    extern __shared__ char sm[];
    const uint32_t sb = smem_u32(sm);
    const int tid = threadIdx.x;
    const int lane = tid & 31, w = tid >> 5;
    const int qt = gridDim.x - 1 - (int)blockIdx.x;    // long blocks first
    const int bh = blockIdx.y;
    const int b = bh >> 4, h = bh & 15;

    const __nv_bfloat16* Qhg = g_Qh + (size_t)bh*SEQ*DK + (size_t)qt*128*DK;
    const __nv_bfloat16* Qlg = g_Ql + (size_t)bh*SEQ*DK + (size_t)qt*128*DK;
    const __nv_bfloat16* Khg = g_Kh + (size_t)bh*SEQ*DK;
    const __nv_bfloat16* Klg = g_Kl + (size_t)bh*SEQ*DK;
    const __nv_bfloat16* Vhg = g_Vth + (size_t)bh*DK*SEQ;
    const __nv_bfloat16* Vlg = g_Vtl + (size_t)bh*DK*SEQ;

    const uint32_t QH = sb + 2*FSTG, QL = QH + 18432u;

    #pragma unroll
    for (int i = 0; i < 4; i++) {
        int idx = tid + i*256;
        int r = idx >> 3, c = idx & 7;
        CP16(QH + r*144 + c*16, Qhg + r*64 + c*8);
        CP16(QL + r*144 + c*16, Qlg + r*64 + c*8);
    }
    CPC();
    flash_load_kv(sb, Khg, Klg, Vhg, Vlg, 0, tid);
    CPC();
    CPW(1);
    __syncthreads();

    uint32_t qfh[4][4], qfl[4][4];
    const uint32_t a_off = (uint32_t)((w*16 + (lane & 15))*144) + (uint32_t)((lane >> 4)*16);
    #pragma unroll
    for (int kc = 0; kc < 4; kc++) {
        ldsm4(qfh[kc], QH + a_off + kc*32);
        ldsm4(qfl[kc], QL + a_off + kc*32);
    }

    if (qt >= 1) {
        flash_load_kv(sb + FSTG, Khg, Klg, Vhg, Vlg, 1, tid);
        CPC();
    }

    const uint32_t kb_off = (uint32_t)(((lane & 7) + ((lane >> 4)*8))*144)
                          + (uint32_t)(((lane >> 3) & 1)*16);
    const uint32_t vb_off = (uint32_t)(((lane & 7) + ((lane >> 4)*8))*272)
                          + (uint32_t)(((lane >> 3) & 1)*16);

    float o[8][4];
    #pragma unroll
    for (int dt = 0; dt < 8; dt++)
        #pragma unroll
        for (int q = 0; q < 4; q++) o[dt][q] = 0.f;
    float l0 = 0.f, l1 = 0.f;

    for (int kt = 0; kt <= qt; kt++) {
        if (kt < qt) { CPW(1); } else { CPW(0); }
        __syncthreads();
        if (kt + 2 <= qt) {
            flash_load_kv(sb + (uint32_t)((kt+2)%3)*FSTG, Khg, Klg, Vhg, Vlg, kt + 2, tid);
            CPC();
        }

        const uint32_t st = sb + (uint32_t)(kt%3)*FSTG;

        float acc[16][4];
        #pragma unroll
        for (int nt = 0; nt < 16; nt++)
            #pragma unroll
            for (int q = 0; q < 4; q++) acc[nt][q] = 0.f;

        #pragma unroll
        for (int kc = 0; kc < 4; kc++) {
            #pragma unroll
            for (int g = 0; g < 8; g++) {
                uint32_t bh4[4], bl4[4];
                ldsm4(bh4, st + kb_off + g*2304u + kc*32);
                ldsm4(bl4, st + F_KL + kb_off + g*2304u + kc*32);
                #pragma unroll
                for (int sub = 0; sub < 2; sub++) {
                    int nt = g*2 + sub;
                    mma16816(acc[nt], qfh[kc], bh4[sub*2], bh4[sub*2+1]);
                    mma16816(acc[nt], qfl[kc], bh4[sub*2], bh4[sub*2+1]);
                    mma16816(acc[nt], qfh[kc], bl4[sub*2], bl4[sub*2+1]);
                }
            }
        }

        if (kt == qt) {
            #pragma unroll
            for (int nt = 0; nt < 16; nt++)
                #pragma unroll
                for (int j = 0; j < 4; j++) {
                    int kj = kt*128 + nt*8 + ((lane & 3) << 1) + (j & 1);
                    int qi = qt*128 + w*16 + (lane >> 2) + ((j >> 1) << 3);
                    if (kj > qi) acc[nt][j] = -1e30f;
                }
        }

        #pragma unroll
        for (int nt = 0; nt < 16; nt++) {
            acc[nt][0] = exp2m12(acc[nt][0]);
            acc[nt][1] = exp2m12(acc[nt][1]);
            acc[nt][2] = exp2m12(acc[nt][2]);
            acc[nt][3] = exp2m12(acc[nt][3]);
            l0 += acc[nt][0] + acc[nt][1];
            l1 += acc[nt][2] + acc[nt][3];
        }

        #pragma unroll
        for (int kc = 0; kc < 8; kc++) {
            uint32_t pah[4], pal[4];
            pah[0] = cvt2(acc[2*kc][0],   acc[2*kc][1]);   pal[0] = cvt2res(acc[2*kc][0],   acc[2*kc][1],   pah[0]);
            pah[1] = cvt2(acc[2*kc][2],   acc[2*kc][3]);   pal[1] = cvt2res(acc[2*kc][2],   acc[2*kc][3],   pah[1]);
            pah[2] = cvt2(acc[2*kc+1][0], acc[2*kc+1][1]); pal[2] = cvt2res(acc[2*kc+1][0], acc[2*kc+1][1], pah[2]);
            pah[3] = cvt2(acc[2*kc+1][2], acc[2*kc+1][3]); pal[3] = cvt2res(acc[2*kc+1][2], acc[2*kc+1][3], pah[3]);
            uint32_t vbh[4][4], vbl[4][4];
            #pragma unroll
            for (int g = 0; g < 4; g++) {
                ldsm4(vbh[g], st + F_VH + vb_off + g*4352u + kc*32);
                ldsm4(vbl[g], st + F_VL + vb_off + g*4352u + kc*32);
            }
            #pragma unroll
            for (int dt = 0; dt < 8; dt++) {
                uint32_t b0 = vbh[dt>>1][(dt&1)*2], b1 = vbh[dt>>1][(dt&1)*2+1];
                uint32_t c0 = vbl[dt>>1][(dt&1)*2], c1 = vbl[dt>>1][(dt&1)*2+1];
                mma16816(o[dt], pah, b0, b1);
                mma16816(o[dt], pal, b0, b1);
                mma16816(o[dt], pah, c0, c1);
            }
        }
    }

    l0 += __shfl_xor_sync(0xffffffffu, l0, 1);
    l0 += __shfl_xor_sync(0xffffffffu, l0, 2);
    l1 += __shfl_xor_sync(0xffffffffu, l1, 1);
    l1 += __shfl_xor_sync(0xffffffffu, l1, 2);
    float inv0 = 1.0f / l0, inv1 = 1.0f / l1;
    int r0 = qt*128 + w*16 + (lane >> 2);
    #pragma unroll
    for (int dt = 0; dt < 8; dt++) {
        int d = dt*8 + (lane & 3)*2;
        size_t p0 = ((size_t)b*SEQ + r0)*D_MODEL + h*64 + d;
        size_t p1 = p0 + (size_t)8*D_MODEL;
        float a0 = o[dt][0]*inv0, a1 = o[dt][1]*inv0;
        float a2 = o[dt][2]*inv1, a3 = o[dt][3]*inv1;
        uint32_t h0 = cvt2(a0, a1), h1v = cvt2(a2, a3);
        *(uint32_t*)(g_Ah + p0) = h0;
        *(uint32_t*)(g_Al + p0) = cvt2res(a0, a1, h0);
        *(uint32_t*)(g_Ah + p1) = h1v;
        *(uint32_t*)(g_Al + p1) = cvt2res(a2, a3, h1v);
    }
}

// ---------------- launch ----------------
extern "C" void kernel_launch(void* const* d_in, const int* in_sizes, int n_in,
                              void* d_out, int out_size)
{
    const float* x  = (const float*)d_in[0];
    const float* Wq = (const float*)d_in[1];
    const float* Wk = (const float*)d_in[2];
    const float* Wv = (const float*)d_in[3];
    const float* Wo = (const float*)d_in[4];
    float* out = (float*)d_out;

    const int gemm_smem  = 2*GST;      // 221184 B
    const int flash_smem = 3*FSTG;     // 215040 B
    cudaFuncSetAttribute(tc_qkv_kernel, cudaFuncAttributeMaxDynamicSharedMemorySize, gemm_smem);
    cudaFuncSetAttribute(tc_out_kernel, cudaFuncAttributeMaxDynamicSharedMemorySize, gemm_smem);
    cudaFuncSetAttribute(flash_kernel,  cudaFuncAttributeMaxDynamicSharedMemorySize, flash_smem);

    rope_table_kernel<<<(SEQ*(DK/2) + 255)/256, 256>>>();

    const size_t NTOT = (size_t)MTOT*D_MODEL + 4*(size_t)D_MODEL*D_MODEL;   // 8M
    split_all_kernel<<<(int)(NTOT/4/256), 256>>>(x, Wq, Wk, Wv, Wo);

    dim3 g1(D_MODEL/128, MTOT/256, 3);
    tc_qkv_kernel<<<g1, 512, gemm_smem>>>();

    dim3 g2(SEQ/128, NBH);
    flash_kernel<<<g2, 256, flash_smem>>>();

    dim3 g3(D_MODEL/128, MTOT/256);
    tc_out_kernel<<<g3, 512, gemm_smem>>>(out);
}

// round 16
// speedup vs baseline: 1.0548x; 1.0235x over previous
#include <cuda_runtime.h>
#include <cuda_bf16.h>
#include <cstdint>
#include <math.h>

#define D_MODEL 1024
#define NHEADS  16
#define DK      64
#define SEQ     2048
#define BATCH   2
#define MTOT    (BATCH*SEQ)
#define NBH     (BATCH*NHEADS)

// ---- device scratch (no cudaMalloc allowed) ----
__device__ __nv_bfloat16 g_xh[(size_t)MTOT*D_MODEL];
__device__ __nv_bfloat16 g_xl[(size_t)MTOT*D_MODEL];
__device__ __nv_bfloat16 g_Wh[4][(size_t)D_MODEL*D_MODEL];   // q,k,v,o
__device__ __nv_bfloat16 g_Wl[4][(size_t)D_MODEL*D_MODEL];
__device__ __nv_bfloat16 g_Qh[(size_t)NBH*SEQ*DK];
__device__ __nv_bfloat16 g_Ql[(size_t)NBH*SEQ*DK];
__device__ __nv_bfloat16 g_Kh[(size_t)NBH*SEQ*DK];
__device__ __nv_bfloat16 g_Kl[(size_t)NBH*SEQ*DK];
__device__ __nv_bfloat16 g_Vth[(size_t)NBH*DK*SEQ];   // transposed: [bh][d][s]
__device__ __nv_bfloat16 g_Vtl[(size_t)NBH*DK*SEQ];
__device__ __nv_bfloat16 g_Ah[(size_t)MTOT*D_MODEL];  // attention out, split
__device__ __nv_bfloat16 g_Al[(size_t)MTOT*D_MODEL];
__device__ float g_cos[SEQ*(DK/2)];
__device__ float g_sin[SEQ*(DK/2)];

// =============== helpers ===============
__device__ __forceinline__ uint32_t smem_u32(const void* p) {
    uint32_t a;
    asm("{ .reg .u64 t; cvta.to.shared.u64 t, %1; cvt.u32.u64 %0, t; }" : "=r"(a) : "l"(p));
    return a;
}
__device__ __forceinline__ void ldsm4(uint32_t* r, uint32_t a) {
    asm volatile("ldmatrix.sync.aligned.m8n8.x4.shared.b16 {%0,%1,%2,%3}, [%4];"
        : "=r"(r[0]), "=r"(r[1]), "=r"(r[2]), "=r"(r[3]) : "r"(a));
}
__device__ __forceinline__ void mma16816(float* d, const uint32_t* a, uint32_t b0, uint32_t b1) {
    asm volatile("mma.sync.aligned.m16n8k16.row.col.f32.bf16.bf16.f32 "
        "{%0,%1,%2,%3},{%4,%5,%6,%7},{%8,%9},{%0,%1,%2,%3};"
        : "+f"(d[0]), "+f"(d[1]), "+f"(d[2]), "+f"(d[3])
        : "r"(a[0]), "r"(a[1]), "r"(a[2]), "r"(a[3]), "r"(b0), "r"(b1));
}
__device__ __forceinline__ uint32_t cvt2(float a, float b) {
    __nv_bfloat162 t = __floats2bfloat162_rn(a, b);
    return *(uint32_t*)&t;
}
__device__ __forceinline__ uint32_t cvt2res(float a, float b, uint32_t h) {
    __nv_bfloat162 th = *(__nv_bfloat162*)&h;
    return cvt2(a - __low2float(th), b - __high2float(th));
}
#define CP16(d, s) asm volatile("cp.async.cg.shared.global [%0], [%1], 16;" :: "r"(d), "l"(s))
#define CPC()      asm volatile("cp.async.commit_group;" ::: "memory")
#define CPW(n)     asm volatile("cp.async.wait_group %0;" :: "n"(n) : "memory")
#define BARG(id)   asm volatile("bar.sync %0, 256;" :: "r"(id) : "memory")

// ---------------- RoPE table ----------------
__global__ void rope_table_kernel() {
    int i = blockIdx.x*blockDim.x + threadIdx.x;
    if (i >= SEQ*(DK/2)) return;
    int s = i / (DK/2);
    int j = i % (DK/2);
    double freq = pow(10000.0, -(double)(2*j)/(double)DK);
    double ang  = (double)s * freq;
    g_cos[i] = (float)cos(ang);
    g_sin[i] = (float)sin(ang);
}

// exp2(x - 12) with the shift folded into the range-reduction magic constant.
__device__ __forceinline__ float exp2m12(float x) {
    x = fmaxf(x, -113.0f);
    float t = x + 12582900.0f;               // (x-12) + 1.5*2^23
    int   e = __float_as_int(t) << 23;
    float f = x - (t - 12582900.0f);
    float p = 1.5402387e-4f;
    p = fmaf(p, f, 1.3333558e-3f);
    p = fmaf(p, f, 9.6181291e-3f);
    p = fmaf(p, f, 5.5504109e-2f);
    p = fmaf(p, f, 2.4022651e-1f);
    p = fmaf(p, f, 6.9314718e-1f);
    p = fmaf(p, f, 1.0f);
    return __int_as_float(__float_as_int(p) + e);
}

// ---------------- fp32 -> bf16 h/l split (single merged pre-pass) ----------------
__global__ void split_all_kernel(const float* __restrict__ x,
                                 const float* __restrict__ Wq,
                                 const float* __restrict__ Wk,
                                 const float* __restrict__ Wv,
                                 const float* __restrict__ Wo)
{
    size_t i = ((size_t)blockIdx.x*blockDim.x + threadIdx.x) * 4;
    const float* s;
    __nv_bfloat16 *h, *l;
    size_t off;
    const size_t NX = (size_t)MTOT*D_MODEL;
    if (i < NX) {
        s = x; h = g_xh; l = g_xl; off = i;
    } else {
        size_t j = i - NX;
        int w = (int)(j >> 20);
        off = j & ((1u << 20) - 1);
        s = (w == 0) ? Wq : (w == 1) ? Wk : (w == 2) ? Wv : Wo;
        h = g_Wh[w]; l = g_Wl[w];
    }
    float4 v = *(const float4*)(s + off);
    uint32_t h0 = cvt2(v.x, v.y), h1 = cvt2(v.z, v.w);
    uint32_t l0 = cvt2res(v.x, v.y, h0), l1 = cvt2res(v.z, v.w, h1);
    *(uint2*)(h + off) = make_uint2(h0, h1);
    *(uint2*)(l + off) = make_uint2(l0, l1);
}

// =============== bf16 pre-split GEMM core (R15-proven: CTA 256x128, 512 thr, warp 64x32) ===============
#define GST  110592u
#define G_AL 36864u
#define G_BH 73728u
#define G_BL 92160u

__device__ __forceinline__ void gemm_load_stage(
    uint32_t stg, const __nv_bfloat16* Ah, const __nv_bfloat16* Al,
    const __nv_bfloat16* Bh, const __nv_bfloat16* Bl, int koff, int tid)
{
    #pragma unroll
    for (int i = 0; i < 4; i++) {
        int idx = tid + i*512;
        int r = idx >> 3, cb = idx & 7;
        uint32_t dst = stg + (uint32_t)r*144u + (uint32_t)cb*16u;
        size_t src = (size_t)r*D_MODEL + koff + cb*8;
        CP16(dst,        Ah + src);
        CP16(dst + G_AL, Al + src);
    }
    #pragma unroll
    for (int i = 0; i < 2; i++) {
        int idx = tid + i*512;
        int r = idx >> 3, cb = idx & 7;
        uint32_t dst = stg + G_BH + (uint32_t)r*144u + (uint32_t)cb*16u;
        size_t src = (size_t)r*D_MODEL + koff + cb*8;
        CP16(dst,                  Bh + src);
        CP16(dst + (G_BL - G_BH),  Bl + src);
    }
}

__device__ __forceinline__ void bf16_gemm_core2(
    const __nv_bfloat16* __restrict__ Ah, const __nv_bfloat16* __restrict__ Al,
    const __nv_bfloat16* __restrict__ Bh, const __nv_bfloat16* __restrict__ Bl,
    char* sm, int tid, float acc[4][4][4])
{
    const int lane = tid & 31, warp = tid >> 5;
    const int wm = warp >> 2, wn = warp & 3;
    const uint32_t sb = smem_u32(sm);
    const uint32_t a_off = (uint32_t)(wm*64 + (lane & 15))*144u + (uint32_t)((lane >> 4)*16);
    const uint32_t b_off = (uint32_t)(wn*32 + (lane & 7) + ((lane >> 4)*8))*144u
                         + (uint32_t)(((lane >> 3) & 1)*16);

    #pragma unroll
    for (int mt = 0; mt < 4; mt++)
        #pragma unroll
        for (int nt = 0; nt < 4; nt++)
            #pragma unroll
            for (int q = 0; q < 4; q++) acc[mt][nt][q] = 0.f;

    gemm_load_stage(sb, Ah, Al, Bh, Bl, 0, tid);
    CPC();

    for (int c = 0; c < 16; c++) {
        if (c < 15) {
            gemm_load_stage(sb + ((c+1) & 1)*GST, Ah, Al, Bh, Bl, (c+1)*64, tid);
            CPC();
            CPW(1);
        } else {
            CPW(0);
        }
        __syncthreads();

        const uint32_t stg = sb + (c & 1)*GST;
        #pragma unroll
        for (int kc = 0; kc < 4; kc++) {
            uint32_t aH[4][4], aL[4][4];
            #pragma unroll
            for (int j = 0; j < 4; j++) {
                ldsm4(aH[j], stg + a_off + j*2304u + kc*32);
                ldsm4(aL[j], stg + G_AL + a_off + j*2304u + kc*32);
            }
            #pragma unroll
            for (int g = 0; g < 2; g++) {
                uint32_t bh4[4], bl4[4];
                ldsm4(bh4, stg + G_BH + b_off + g*2304u + kc*32);
                ldsm4(bl4, stg + G_BL + b_off + g*2304u + kc*32);
                #pragma unroll
                for (int sub = 0; sub < 2; sub++) {
                    int nt = g*2 + sub;
                    uint32_t b0 = bh4[sub*2], b1 = bh4[sub*2+1];
                    uint32_t c0 = bl4[sub*2], c1 = bl4[sub*2+1];
                    #pragma unroll
                    for (int mt = 0; mt < 4; mt++) {
                        mma16816(acc[mt][nt], aH[mt], b0, b1);
                        mma16816(acc[mt][nt], aL[mt], b0, b1);
                        mma16816(acc[mt][nt], aH[mt], c0, c1);
                    }
                }
            }
        }
        __syncthreads();
    }
}

// =============== fused QKV GEMM + RoPE + bf16-split store ===============
__global__ __launch_bounds__(512) void tc_qkv_kernel()
{
    extern __shared__ char sm[];
    const int tid = threadIdx.x;
    const int z = blockIdx.z;
    const int m0 = blockIdx.y * 256;
    const int n0 = blockIdx.x * 128;
    const float SCQ = 0.18033688011112042f;   // log2(e)/sqrt(64)

    float acc[4][4][4];
    bf16_gemm_core2(g_xh + (size_t)m0*D_MODEL, g_xl + (size_t)m0*D_MODEL,
                    g_Wh[z] + (size_t)n0*D_MODEL, g_Wl[z] + (size_t)n0*D_MODEL,
                    sm, tid, acc);

    const int lane = tid & 31, warp = tid >> 5;
    const int wm = warp >> 2, wn = warp & 3;

    #pragma unroll
    for (int mt = 0; mt < 4; mt++) {
        #pragma unroll
        for (int rr = 0; rr < 2; rr++) {
            int m = m0 + wm*64 + mt*16 + (lane >> 2) + rr*8;
            int b = m >> 11, s = m & (SEQ-1);
            int bh = b*NHEADS;
            #pragma unroll
            for (int nt = 0; nt < 4; nt++) {
                int n = n0 + wn*32 + nt*8 + (lane & 3)*2;
                int h = n >> 6, d = n & 63;
                float x1 = acc[mt][nt][rr*2], x2 = acc[mt][nt][rr*2+1];
                if (z < 2) {
                    float cv = g_cos[s*(DK/2) + (d >> 1)];
                    float sv = g_sin[s*(DK/2) + (d >> 1)];
                    float o1 = cv*x1 - sv*x2;
                    float o2 = sv*x1 + cv*x2;
                    if (z == 0) { o1 *= SCQ; o2 *= SCQ; }
                    uint32_t hv = cvt2(o1, o2);
                    uint32_t lv = cvt2res(o1, o2, hv);
                    size_t base = ((size_t)(bh + h)*SEQ + s)*DK + d;
                    if (z == 0) {
                        *(uint32_t*)(g_Qh + base) = hv;
                        *(uint32_t*)(g_Ql + base) = lv;
                    } else {
                        *(uint32_t*)(g_Kh + base) = hv;
                        *(uint32_t*)(g_Kl + base) = lv;
                    }
                } else {
                    size_t tb = ((size_t)(bh + h)*DK + d)*SEQ + s;
                    __nv_bfloat16 h1 = __float2bfloat16_rn(x1);
                    __nv_bfloat16 h2 = __float2bfloat16_rn(x2);
                    g_Vth[tb]       = h1;
                    g_Vth[tb + SEQ] = h2;
                    g_Vtl[tb]       = __float2bfloat16_rn(x1 - __bfloat162float(h1));
                    g_Vtl[tb + SEQ] = __float2bfloat16_rn(x2 - __bfloat162float(h2));
                }
            }
        }
    }
}

// =============== output projection ===============
__global__ __launch_bounds__(512) void tc_out_kernel(float* __restrict__ out)
{
    extern __shared__ char sm[];
    const int tid = threadIdx.x;
    const int m0 = blockIdx.y * 256;
    const int n0 = blockIdx.x * 128;

    float acc[4][4][4];
    bf16_gemm_core2(g_Ah + (size_t)m0*D_MODEL, g_Al + (size_t)m0*D_MODEL,
                    g_Wh[3] + (size_t)n0*D_MODEL, g_Wl[3] + (size_t)n0*D_MODEL,
                    sm, tid, acc);

    const int lane = tid & 31, warp = tid >> 5;
    const int wm = warp >> 2, wn = warp & 3;

    #pragma unroll
    for (int mt = 0; mt < 4; mt++) {
        #pragma unroll
        for (int rr = 0; rr < 2; rr++) {
            int m = m0 + wm*64 + mt*16 + (lane >> 2) + rr*8;
            #pragma unroll
            for (int nt = 0; nt < 4; nt++) {
                int n = n0 + wn*32 + nt*8 + (lane & 3)*2;
                *(float2*)(out + (size_t)m*D_MODEL + n) =
                    make_float2(acc[mt][nt][rr*2], acc[mt][nt][rr*2+1]);
            }
        }
    }
}

// =============== flash attention: 2 independent warp groups (BN=64 each) ===============
// 512 threads = 2 groups x 8 warps. Group g handles kv tiles kt64 = 2t+g, t=0..qt.
// Each group: own double-buffered stages + named barrier; o/l combined at epilogue.
// Stage (36864B): Kh@0 Kl@9216 Vth@18432 Vtl@27648 (64 rows x 144B each).
#define FST64 36864u

__device__ __forceinline__ void flash_load_kv64(
    uint32_t st, const __nv_bfloat16* Khg, const __nv_bfloat16* Klg,
    const __nv_bfloat16* Vhg, const __nv_bfloat16* Vlg, int kt64, int tg)
{
    const __nv_bfloat16* kh = Khg + (size_t)kt64*64*DK;
    const __nv_bfloat16* kl = Klg + (size_t)kt64*64*DK;
    #pragma unroll
    for (int i = 0; i < 2; i++) {
        int idx = tg + i*256;
        int r = idx >> 3, c = idx & 7;                 // 64 rows x 8 chunks
        CP16(st + r*144 + c*16,          kh + r*64 + c*8);
        CP16(st + 9216u + r*144 + c*16,  kl + r*64 + c*8);
        CP16(st + 18432u + r*144 + c*16, Vhg + (size_t)r*SEQ + kt64*64 + c*8);
        CP16(st + 27648u + r*144 + c*16, Vlg + (size_t)r*SEQ + kt64*64 + c*8);
    }
}

__global__ __launch_bounds__(512,1) void flash_kernel()
{
    extern __shared__ char sm[];
    const uint32_t sb = smem_u32(sm);
    const int tid = threadIdx.x;
    const int lane = tid & 31, w = tid >> 5;
    const int grp = w >> 3, mw = w & 7;
    const int tg = tid & 255;
    const int bar_id = 1 + grp;
    const int qt = gridDim.x - 1 - (int)blockIdx.x;    // long blocks first
    const int bh = blockIdx.y;
    const int b = bh >> 4, h = bh & 15;

    const __nv_bfloat16* Qhg = g_Qh + (size_t)bh*SEQ*DK + (size_t)qt*128*DK;
    const __nv_bfloat16* Qlg = g_Ql + (size_t)bh*SEQ*DK + (size_t)qt*128*DK;
    const __nv_bfloat16* Khg = g_Kh + (size_t)bh*SEQ*DK;
    const __nv_bfloat16* Klg = g_Kl + (size_t)bh*SEQ*DK;
    const __nv_bfloat16* Vhg = g_Vth + (size_t)bh*DK*SEQ;
    const __nv_bfloat16* Vlg = g_Vtl + (size_t)bh*DK*SEQ;

    const uint32_t gbase = sb + (uint32_t)grp*2u*FST64;    // this group's two stages
    const uint32_t QH = sb + 4u*FST64, QL = QH + 18432u;

    // Q cooperative load (all 512 threads)
    #pragma unroll
    for (int i = 0; i < 2; i++) {
        int idx = tid + i*512;
        int r = idx >> 3, c = idx & 7;
        CP16(QH + r*144 + c*16, Qhg + r*64 + c*8);
        CP16(QL + r*144 + c*16, Qlg + r*64 + c*8);
    }
    CPC();
    // group stage 0 (tile t=0 -> kt64 = grp)
    flash_load_kv64(gbase, Khg, Klg, Vhg, Vlg, grp, tg);
    CPC();
    // prefetch t=1 if it exists
    if (qt >= 1) {
        flash_load_kv64(gbase + FST64, Khg, Klg, Vhg, Vlg, 2 + grp, tg);
        CPC();
        CPW(1);     // Q + stage0 done
    } else {
        CPW(0);
    }
    __syncthreads();   // Q visible CTA-wide (loaded by both groups' threads)

    const uint32_t a_off  = (uint32_t)((mw*16 + (lane & 15))*144) + (uint32_t)((lane >> 4)*16);
    const uint32_t kb_off = (uint32_t)(((lane & 7) + ((lane >> 4)*8))*144)
                          + (uint32_t)(((lane >> 3) & 1)*16);
    const uint32_t vb_off = kb_off;    // V tile has same [64 x 144B] geometry

    float o[8][4];
    #pragma unroll
    for (int dt = 0; dt < 8; dt++)
        #pragma unroll
        for (int q = 0; q < 4; q++) o[dt][q] = 0.f;
    float l0 = 0.f, l1 = 0.f;

    for (int t = 0; t <= qt; t++) {
        if (t < qt) { CPW(1); } else { CPW(0); }
        BARG(bar_id);                      // stage t visible group-wide

        const uint32_t st = gbase + (uint32_t)(t & 1)*FST64;

        // ---- QK^T: 8 n-tiles over this group's 64 kv ----
        float acc[8][4];
        #pragma unroll
        for (int nt = 0; nt < 8; nt++)
            #pragma unroll
            for (int q = 0; q < 4; q++) acc[nt][q] = 0.f;

        #pragma unroll
        for (int kc = 0; kc < 4; kc++) {
            uint32_t qh4[4], ql4[4];
            ldsm4(qh4, QH + a_off + kc*32);
            ldsm4(ql4, QL + a_off + kc*32);
            #pragma unroll
            for (int g = 0; g < 4; g++) {
                uint32_t bh4[4], bl4[4];
                ldsm4(bh4, st + kb_off + g*2304u + kc*32);
                ldsm4(bl4, st + 9216u + kb_off + g*2304u + kc*32);
                #pragma unroll
                for (int sub = 0; sub < 2; sub++) {
                    int nt = g*2 + sub;
                    mma16816(acc[nt], qh4, bh4[sub*2], bh4[sub*2+1]);
                    mma16816(acc[nt], ql4, bh4[sub*2], bh4[sub*2+1]);
                    mma16816(acc[nt], qh4, bl4[sub*2], bl4[sub*2+1]);
                }
            }
        }

        // ---- causal mask (group's last tile only) ----
        if (t == qt) {
            const int lt = 2*qt + grp;
            #pragma unroll
            for (int nt = 0; nt < 8; nt++)
                #pragma unroll
                for (int j = 0; j < 4; j++) {
                    int kj = lt*64 + nt*8 + ((lane & 3) << 1) + (j & 1);
                    int qi = qt*128 + mw*16 + (lane >> 2) + ((j >> 1) << 3);
                    if (kj > qi) acc[nt][j] = -1e30f;
                }
        }

        // ---- static-max softmax ----
        #pragma unroll
        for (int nt = 0; nt < 8; nt++) {
            acc[nt][0] = exp2m12(acc[nt][0]);
            acc[nt][1] = exp2m12(acc[nt][1]);
            acc[nt][2] = exp2m12(acc[nt][2]);
            acc[nt][3] = exp2m12(acc[nt][3]);
            l0 += acc[nt][0] + acc[nt][1];
            l1 += acc[nt][2] + acc[nt][3];
        }

        // ---- PV over group's 64 kv: 4 k-chunks of 16 ----
        #pragma unroll
        for (int kc = 0; kc < 4; kc++) {
            uint32_t pah[4], pal[4];
            pah[0] = cvt2(acc[2*kc][0],   acc[2*kc][1]);   pal[0] = cvt2res(acc[2*kc][0],   acc[2*kc][1],   pah[0]);
            pah[1] = cvt2(acc[2*kc][2],   acc[2*kc][3]);   pal[1] = cvt2res(acc[2*kc][2],   acc[2*kc][3],   pah[1]);
            pah[2] = cvt2(acc[2*kc+1][0], acc[2*kc+1][1]); pal[2] = cvt2res(acc[2*kc+1][0], acc[2*kc+1][1], pah[2]);
            pah[3] = cvt2(acc[2*kc+1][2], acc[2*kc+1][3]); pal[3] = cvt2res(acc[2*kc+1][2], acc[2*kc+1][3], pah[3]);
            uint32_t vbh[4][4], vbl[4][4];
            #pragma unroll
            for (int g = 0; g < 4; g++) {
                ldsm4(vbh[g], st + 18432u + vb_off + g*2304u + kc*32);
                ldsm4(vbl[g], st + 27648u + vb_off + g*2304u + kc*32);
            }
            #pragma unroll
            for (int dt = 0; dt < 8; dt++) {
                uint32_t b0 = vbh[dt>>1][(dt&1)*2], b1 = vbh[dt>>1][(dt&1)*2+1];
                uint32_t c0 = vbl[dt>>1][(dt&1)*2], c1 = vbl[dt>>1][(dt&1)*2+1];
                mma16816(o[dt], pah, b0, b1);
                mma16816(o[dt], pal, b0, b1);
                mma16816(o[dt], pah, c0, c1);
            }
        }

        BARG(bar_id);                      // group reads of stage t complete
        if (t + 2 <= qt) {
            flash_load_kv64(gbase + (uint32_t)(t & 1)*FST64, Khg, Klg, Vhg, Vlg, 2*(t+2) + grp, tg);
            CPC();
        }
    }

    // ---- epilogue: combine groups, normalize, write bf16 h/l split ----
    __syncthreads();
    float* red = (float*)sm;     // 8 warps x 32 lanes x 34 floats = 34816 B (reuses group-0 stage)
    if (grp == 1) {
        float* dst = red + ((size_t)(mw*32 + lane))*34;
        #pragma unroll
        for (int dt = 0; dt < 8; dt++)
            #pragma unroll
            for (int q = 0; q < 4; q++) dst[dt*4+q] = o[dt][q];
        dst[32] = l0;
        dst[33] = l1;
    }
    __syncthreads();
    if (grp == 0) {
        const float* src = red + ((size_t)(mw*32 + lane))*34;
        #pragma unroll
        for (int dt = 0; dt < 8; dt++)
            #pragma unroll
            for (int q = 0; q < 4; q++) o[dt][q] += src[dt*4+q];
        l0 += src[32];
        l1 += src[33];

        l0 += __shfl_xor_sync(0xffffffffu, l0, 1);
        l0 += __shfl_xor_sync(0xffffffffu, l0, 2);
        l1 += __shfl_xor_sync(0xffffffffu, l1, 1);
        l1 += __shfl_xor_sync(0xffffffffu, l1, 2);
        float inv0 = 1.0f / l0, inv1 = 1.0f / l1;
        int r0 = qt*128 + mw*16 + (lane >> 2);
        #pragma unroll
        for (int dt = 0; dt < 8; dt++) {
            int d = dt*8 + (lane & 3)*2;
            size_t p0 = ((size_t)b*SEQ + r0)*D_MODEL + h*64 + d;
            size_t p1 = p0 + (size_t)8*D_MODEL;
            float a0 = o[dt][0]*inv0, a1 = o[dt][1]*inv0;
            float a2 = o[dt][2]*inv1, a3 = o[dt][3]*inv1;
            uint32_t h0 = cvt2(a0, a1), h1v = cvt2(a2, a3);
            *(uint32_t*)(g_Ah + p0) = h0;
            *(uint32_t*)(g_Al + p0) = cvt2res(a0, a1, h0);
            *(uint32_t*)(g_Ah + p1) = h1v;
            *(uint32_t*)(g_Al + p1) = cvt2res(a2, a3, h1v);
        }
    }
}

// ---------------- launch ----------------
extern "C" void kernel_launch(void* const* d_in, const int* in_sizes, int n_in,
                              void* d_out, int out_size)
{
    const float* x  = (const float*)d_in[0];
    const float* Wq = (const float*)d_in[1];
    const float* Wk = (const float*)d_in[2];
    const float* Wv = (const float*)d_in[3];
    const float* Wo = (const float*)d_in[4];
    float* out = (float*)d_out;

    const int gemm_smem  = 2*GST;                  // 221184 B
    const int flash_smem = 4*FST64 + 36864;        // 184320 B
    cudaFuncSetAttribute(tc_qkv_kernel, cudaFuncAttributeMaxDynamicSharedMemorySize, gemm_smem);
    cudaFuncSetAttribute(tc_out_kernel, cudaFuncAttributeMaxDynamicSharedMemorySize, gemm_smem);
    cudaFuncSetAttribute(flash_kernel,  cudaFuncAttributeMaxDynamicSharedMemorySize, flash_smem);

    rope_table_kernel<<<(SEQ*(DK/2) + 255)/256, 256>>>();

    const size_t NTOT = (size_t)MTOT*D_MODEL + 4*(size_t)D_MODEL*D_MODEL;   // 8M
    split_all_kernel<<<(int)(NTOT/4/256), 256>>>(x, Wq, Wk, Wv, Wo);

    dim3 g1(D_MODEL/128, MTOT/256, 3);
    tc_qkv_kernel<<<g1, 512, gemm_smem>>>();

    dim3 g2(SEQ/128, NBH);
    flash_kernel<<<g2, 512, flash_smem>>>();

    dim3 g3(D_MODEL/128, MTOT/256);
    tc_out_kernel<<<g3, 512, gemm_smem>>>(out);
}